// round 7
// baseline (speedup 1.0000x reference)
#include <cuda_runtime.h>
#include <cuda_fp16.h>
#include <math.h>
#include <stdint.h>

#define Bq 256
#define Hq 128
#define Nq 2048
#define KK 256          // effective K (decoder folded into bias)
#define BM 128
#define BN 128
#define BK 32
#define AS2 20          // As16[.][h][k2] stride in half2
#define BS2 136         // Bs16[.][k2][n] stride in half2

// ---------------- helpers ----------------
__device__ __forceinline__ float tanh_fast(float x) {
    float y; asm("tanh.approx.f32 %0, %1;" : "=f"(y) : "f"(x)); return y;
}
__device__ __forceinline__ void mma16(float* c, const uint32_t* a, const uint32_t* b) {
    asm volatile(
        "mma.sync.aligned.m16n8k16.row.col.f32.f16.f16.f32 "
        "{%0,%1,%2,%3}, {%4,%5,%6,%7}, {%8,%9}, {%0,%1,%2,%3};"
        : "+f"(c[0]), "+f"(c[1]), "+f"(c[2]), "+f"(c[3])
        : "r"(a[0]), "r"(a[1]), "r"(a[2]), "r"(a[3]), "r"(b[0]), "r"(b[1]));
}
__device__ __forceinline__ uint32_t pack2(float lo, float hi) {
    uint32_t r;
    asm("cvt.rn.f16x2.f32 %0, %2, %1;" : "=r"(r) : "f"(lo), "f"(hi));
    return r;
}

// ---------------------------------------------------------------------------
// Kernel 1: fp16 HMMA GEMM + fused bias + tanh/v-dot -> raw scores
// Double-buffered smem, one __syncthreads per chunk; LDG(c+1) and STS(c+1)
// overlap MMA(c).
// grid (16, 256), 256 threads (8 warps, 4x2 warp grid, 32x64 warp tiles)
// ---------------------------------------------------------------------------
__global__ __launch_bounds__(256, 2) void score_kernel(
    const float* __restrict__ st, const float* __restrict__ dy,
    const float* __restrict__ dec, const float* __restrict__ v,
    const float* __restrict__ W, float* __restrict__ out) {
    __shared__ __align__(16) __half2 As16[2][BM][AS2];
    __shared__ __align__(16) __half2 Bs16[2][BK / 2][BS2];
    __shared__ float vs[Hq];
    __shared__ float cs[Hq];
    __shared__ float red[4][BN];

    const int b  = blockIdx.y;
    const int n0 = blockIdx.x * BN;
    const int t  = threadIdx.x;
    const int w  = t >> 5;
    const int lane = t & 31;
    const int wm = w & 3;
    const int wn = w >> 2;
    const int gid = lane >> 2;
    const int tig = lane & 3;

    // ---- fused bias: cs[h] = W[h][256:384] . dec[b] ----
    if (t < Hq) {
        vs[t] = v[t];
        red[0][t] = dec[b * Hq + t];
    }
    __syncthreads();
    {
        const float* dsh = &red[0][0];
#pragma unroll
        for (int r = 0; r < 16; r++) {
            const int h = w * 16 + r;
            float p = 0.f;
#pragma unroll
            for (int i = 0; i < 4; i++)
                p = fmaf(W[h * 384 + 256 + lane + 32 * i], dsh[lane + 32 * i], p);
#pragma unroll
            for (int off = 16; off; off >>= 1)
                p += __shfl_xor_sync(0xffffffffu, p, off);
            if (lane == 0) cs[h] = p;
        }
    }

    float acc[2][8][4];
#pragma unroll
    for (int i = 0; i < 2; i++)
#pragma unroll
        for (int j = 0; j < 8; j++)
#pragma unroll
            for (int q = 0; q < 4; q++) acc[i][j][q] = 0.f;

    const float* base_st = st + (size_t)b * Hq * Nq;
    const float* base_dy = dy + (size_t)b * Hq * Nq;

    // loader indices (loop-invariant)
    const int ah0 = t >> 2,         aq = t & 3;
    const int ah1 = (t + 256) >> 2;
    const int bk0 = t >> 5,         bc = t & 31;
    const int bk1 = (t + 256) >> 5;

    float4 pa[2][2], pb[2][2];

    // ---- prologue: LDG chunk 0 + pack + STS into buffer 0 ----
    {
        const float* wp0 = &W[ah0 * 384 + aq * 8];
        const float* wp1 = &W[ah1 * 384 + aq * 8];
        pa[0][0] = *(const float4*)wp0;  pa[0][1] = *(const float4*)(wp0 + 4);
        pa[1][0] = *(const float4*)wp1;  pa[1][1] = *(const float4*)(wp1 + 4);
        const float* s0 = base_st + (size_t)(2 * bk0) * Nq + n0 + bc * 4;
        const float* s1 = base_st + (size_t)(2 * bk1) * Nq + n0 + bc * 4;
        pb[0][0] = *(const float4*)s0;   pb[0][1] = *(const float4*)(s0 + Nq);
        pb[1][0] = *(const float4*)s1;   pb[1][1] = *(const float4*)(s1 + Nq);

        uint4 k0, k1;
        k0.x = pack2(pa[0][0].x, pa[0][0].y); k0.y = pack2(pa[0][0].z, pa[0][0].w);
        k0.z = pack2(pa[0][1].x, pa[0][1].y); k0.w = pack2(pa[0][1].z, pa[0][1].w);
        k1.x = pack2(pa[1][0].x, pa[1][0].y); k1.y = pack2(pa[1][0].z, pa[1][0].w);
        k1.z = pack2(pa[1][1].x, pa[1][1].y); k1.w = pack2(pa[1][1].z, pa[1][1].w);
        *(uint4*)&As16[0][ah0][aq * 4] = k0;
        *(uint4*)&As16[0][ah1][aq * 4] = k1;
        uint4 b0, b1;
        b0.x = pack2(pb[0][0].x, pb[0][1].x); b0.y = pack2(pb[0][0].y, pb[0][1].y);
        b0.z = pack2(pb[0][0].z, pb[0][1].z); b0.w = pack2(pb[0][0].w, pb[0][1].w);
        b1.x = pack2(pb[1][0].x, pb[1][1].x); b1.y = pack2(pb[1][0].y, pb[1][1].y);
        b1.z = pack2(pb[1][0].z, pb[1][1].z); b1.w = pack2(pb[1][0].w, pb[1][1].w);
        *(uint4*)&Bs16[0][bk0][bc * 4] = b0;
        *(uint4*)&Bs16[0][bk1][bc * 4] = b1;
    }
    __syncthreads();

    for (int c = 0; c < 8; c++) {
        const int cur = c & 1, nxt = cur ^ 1;

        // ---- issue LDG for chunk c+1 (drains under MMA) ----
        if (c < 7) {
            const int cn = c + 1;
            const float* wp0 = &W[ah0 * 384 + cn * BK + aq * 8];
            const float* wp1 = &W[ah1 * 384 + cn * BK + aq * 8];
            pa[0][0] = *(const float4*)wp0;  pa[0][1] = *(const float4*)(wp0 + 4);
            pa[1][0] = *(const float4*)wp1;  pa[1][1] = *(const float4*)(wp1 + 4);
            const int gk0 = cn * BK + 2 * bk0;
            const int gk1 = cn * BK + 2 * bk1;
            const float* s0 = (gk0 < Hq ? base_st + (size_t)gk0 * Nq
                                        : base_dy + (size_t)(gk0 - Hq) * Nq) + n0 + bc * 4;
            const float* s1 = (gk1 < Hq ? base_st + (size_t)gk1 * Nq
                                        : base_dy + (size_t)(gk1 - Hq) * Nq) + n0 + bc * 4;
            pb[0][0] = *(const float4*)s0;   pb[0][1] = *(const float4*)(s0 + Nq);
            pb[1][0] = *(const float4*)s1;   pb[1][1] = *(const float4*)(s1 + Nq);
        }

        // ---- MMA on current buffer ----
#pragma unroll
        for (int kf = 0; kf < 2; kf++) {
            const int k2 = kf * 8;
            uint32_t a[2][4], bb[8][2];
#pragma unroll
            for (int mf = 0; mf < 2; mf++) {
                const int m = wm * 32 + mf * 16;
                a[mf][0] = *(const uint32_t*)&As16[cur][m + gid][k2 + tig];
                a[mf][1] = *(const uint32_t*)&As16[cur][m + gid + 8][k2 + tig];
                a[mf][2] = *(const uint32_t*)&As16[cur][m + gid][k2 + tig + 4];
                a[mf][3] = *(const uint32_t*)&As16[cur][m + gid + 8][k2 + tig + 4];
            }
#pragma unroll
            for (int nf = 0; nf < 8; nf++) {
                const int n = wn * 64 + nf * 8;
                bb[nf][0] = *(const uint32_t*)&Bs16[cur][k2 + tig][n + gid];
                bb[nf][1] = *(const uint32_t*)&Bs16[cur][k2 + tig + 4][n + gid];
            }
#pragma unroll
            for (int mf = 0; mf < 2; mf++)
#pragma unroll
                for (int nf = 0; nf < 8; nf++)
                    mma16(acc[mf][nf], a[mf], bb[nf]);
        }

        // ---- pack + STS chunk c+1 into the other buffer (overlaps MMA) ----
        if (c < 7) {
            uint4 k0, k1;
            k0.x = pack2(pa[0][0].x, pa[0][0].y); k0.y = pack2(pa[0][0].z, pa[0][0].w);
            k0.z = pack2(pa[0][1].x, pa[0][1].y); k0.w = pack2(pa[0][1].z, pa[0][1].w);
            k1.x = pack2(pa[1][0].x, pa[1][0].y); k1.y = pack2(pa[1][0].z, pa[1][0].w);
            k1.z = pack2(pa[1][1].x, pa[1][1].y); k1.w = pack2(pa[1][1].z, pa[1][1].w);
            *(uint4*)&As16[nxt][ah0][aq * 4] = k0;
            *(uint4*)&As16[nxt][ah1][aq * 4] = k1;
            uint4 b0, b1;
            b0.x = pack2(pb[0][0].x, pb[0][1].x); b0.y = pack2(pb[0][0].y, pb[0][1].y);
            b0.z = pack2(pb[0][0].z, pb[0][1].z); b0.w = pack2(pb[0][0].w, pb[0][1].w);
            b1.x = pack2(pb[1][0].x, pb[1][1].x); b1.y = pack2(pb[1][0].y, pb[1][1].y);
            b1.z = pack2(pb[1][0].z, pb[1][1].z); b1.w = pack2(pb[1][0].w, pb[1][1].w);
            *(uint4*)&Bs16[nxt][bk0][bc * 4] = b0;
            *(uint4*)&Bs16[nxt][bk1][bc * 4] = b1;
        }
        __syncthreads();
    }

    // ---- epilogue: tanh + v-dot, reduce over m ----
#pragma unroll
    for (int nf = 0; nf < 8; nf++) {
        float p0 = 0.f, p1 = 0.f;
#pragma unroll
        for (int mf = 0; mf < 2; mf++) {
            const int r0 = wm * 32 + mf * 16 + gid;
            const int r1 = r0 + 8;
            const float v0 = vs[r0], c0 = cs[r0];
            const float v1 = vs[r1], c1 = cs[r1];
            p0 = fmaf(v0, tanh_fast(acc[mf][nf][0] + c0), p0);
            p1 = fmaf(v0, tanh_fast(acc[mf][nf][1] + c0), p1);
            p0 = fmaf(v1, tanh_fast(acc[mf][nf][2] + c1), p0);
            p1 = fmaf(v1, tanh_fast(acc[mf][nf][3] + c1), p1);
        }
#pragma unroll
        for (int off = 4; off < 32; off <<= 1) {
            p0 += __shfl_xor_sync(0xffffffffu, p0, off);
            p1 += __shfl_xor_sync(0xffffffffu, p1, off);
        }
        if (gid == 0) {
            const int col = wn * 64 + nf * 8 + 2 * tig;
            red[wm][col]     = p0;
            red[wm][col + 1] = p1;
        }
    }
    __syncthreads();

    if (t < BN)
        out[(size_t)b * Nq + n0 + t] =
            red[0][t] + red[1][t] + red[2][t] + red[3][t];
}

// ---------------------------------------------------------------------------
// Kernel 2: in-place row softmax over N=2048
// ---------------------------------------------------------------------------
__global__ __launch_bounds__(256) void softmax_kernel(float* __restrict__ out) {
    __shared__ float sm[8];
    const int b = blockIdx.x, t = threadIdx.x;
    const int w = t >> 5, lane = t & 31;
    float* row = out + (size_t)b * Nq;

    float vals[8];
    float m = -1e30f;
#pragma unroll
    for (int i = 0; i < 8; i++) { vals[i] = row[t + 256 * i]; m = fmaxf(m, vals[i]); }
#pragma unroll
    for (int off = 16; off; off >>= 1)
        m = fmaxf(m, __shfl_xor_sync(0xffffffffu, m, off));
    if (lane == 0) sm[w] = m;
    __syncthreads();
    float M = sm[lane & 7];
#pragma unroll
    for (int off = 4; off; off >>= 1)
        M = fmaxf(M, __shfl_xor_sync(0xffffffffu, M, off));

    float sum = 0.f;
#pragma unroll
    for (int i = 0; i < 8; i++) { vals[i] = __expf(vals[i] - M); sum += vals[i]; }
#pragma unroll
    for (int off = 16; off; off >>= 1)
        sum += __shfl_xor_sync(0xffffffffu, sum, off);
    __syncthreads();
    if (lane == 0) sm[w] = sum;
    __syncthreads();
    float S = sm[lane & 7];
#pragma unroll
    for (int off = 4; off; off >>= 1)
        S += __shfl_xor_sync(0xffffffffu, S, off);

    const float inv = 1.f / S;
#pragma unroll
    for (int i = 0; i < 8; i++) row[t + 256 * i] = vals[i] * inv;
}

// ---------------------------------------------------------------------------
extern "C" void kernel_launch(void* const* d_in, const int* in_sizes, int n_in,
                              void* d_out, int out_size) {
    const float* st  = (const float*)d_in[0];
    const float* dy  = (const float*)d_in[1];
    const float* dec = (const float*)d_in[2];
    const float* v   = (const float*)d_in[3];
    const float* W   = (const float*)d_in[4];
    float* out = (float*)d_out;

    score_kernel<<<dim3(Nq / BN, Bq), 256>>>(st, dy, dec, v, W, out);
    softmax_kernel<<<Bq, 256>>>(out);
}

// round 8
// speedup vs baseline: 1.1438x; 1.1438x over previous
#include <cuda_runtime.h>
#include <cuda_fp16.h>
#include <math.h>
#include <stdint.h>

#define Bq 256
#define Hq 128
#define Nq 2048
#define BM 128
#define BN 128
#define BK 32
#define AS2 20          // As16[.][h][k2] stride in half2 (bank-conflict-free frags)
#define BS2 136         // Bs16[.][k2][n] stride in half2
#define ACHUNKB (BM * AS2 * 4)   // 10240 bytes per packed-A chunk

// Packed W (GEMM slice), laid out exactly as the As16 smem image per chunk:
// g_Wp[((c*128 + h)*20 + k2)] = half2(W[h][32c+2k2], W[h][32c+2k2+1])
__device__ __align__(16) uint32_t g_Wp[8 * BM * AS2];

// ---------------- helpers ----------------
__device__ __forceinline__ float tanh_fast(float x) {
    float y; asm("tanh.approx.f32 %0, %1;" : "=f"(y) : "f"(x)); return y;
}
__device__ __forceinline__ void mma16(float* c, const uint32_t* a, const uint32_t* b) {
    asm volatile(
        "mma.sync.aligned.m16n8k16.row.col.f32.f16.f16.f32 "
        "{%0,%1,%2,%3}, {%4,%5,%6,%7}, {%8,%9}, {%0,%1,%2,%3};"
        : "+f"(c[0]), "+f"(c[1]), "+f"(c[2]), "+f"(c[3])
        : "r"(a[0]), "r"(a[1]), "r"(a[2]), "r"(a[3]), "r"(b[0]), "r"(b[1]));
}
__device__ __forceinline__ uint32_t pack2(float lo, float hi) {
    uint32_t r;
    asm("cvt.rn.f16x2.f32 %0, %2, %1;" : "=r"(r) : "f"(lo), "f"(hi));
    return r;
}
__device__ __forceinline__ void cpa16(uint32_t dst_smem, const void* src) {
    asm volatile("cp.async.ca.shared.global [%0], [%1], 16;"
                 :: "r"(dst_smem), "l"(src) : "memory");
}

// ---------------------------------------------------------------------------
// Kernel 0: pack W[:, 0:256] -> g_Wp (fp16, smem-image layout). 128 x 256 thr.
// ---------------------------------------------------------------------------
__global__ void pack_kernel(const float* __restrict__ W) {
    const int i = blockIdx.x * 256 + threadIdx.x;    // 0..32767
    const int k2 = i & 15;
    const int h  = (i >> 4) & 127;
    const int c  = i >> 11;
    const float2 wv = *(const float2*)&W[h * 384 + c * 32 + 2 * k2];
    g_Wp[(c * BM + h) * AS2 + k2] = pack2(wv.x, wv.y);
}

// ---------------------------------------------------------------------------
// Kernel 1: fp16 HMMA GEMM + fused bias + tanh/v-dot -> raw scores
// A tile arrives via cp.async from pre-packed g_Wp (L2-hot, zero reg cost);
// B tile via register prefetch + pack + STS. Double-buffered, 1 sync/chunk.
// grid (16, 256), 256 threads (8 warps, 4x2 warp grid, 32x64 warp tiles)
// ---------------------------------------------------------------------------
__global__ __launch_bounds__(256, 2) void score_kernel(
    const float* __restrict__ st, const float* __restrict__ dy,
    const float* __restrict__ dec, const float* __restrict__ v,
    const float* __restrict__ W, float* __restrict__ out) {
    __shared__ __align__(16) __half2 As16[2][BM][AS2];
    __shared__ __align__(16) __half2 Bs16[2][BK / 2][BS2];
    __shared__ float vs[Hq];
    __shared__ float cs[Hq];
    __shared__ float red[4][BN];

    const int b  = blockIdx.y;
    const int n0 = blockIdx.x * BN;
    const int t  = threadIdx.x;
    const int w  = t >> 5;
    const int lane = t & 31;
    const int wm = w & 3;
    const int wn = w >> 2;
    const int gid = lane >> 2;
    const int tig = lane & 3;

    const uint32_t sa0 = (uint32_t)__cvta_generic_to_shared(&As16[0][0][0]);
    const uint32_t sa1 = (uint32_t)__cvta_generic_to_shared(&As16[1][0][0]);
    const char* gA = (const char*)g_Wp;

    // ---- kick off A chunk 0 immediately ----
    {
        const char* src = gA;                 // chunk 0
        cpa16(sa0 + t * 16, src + t * 16);
        cpa16(sa0 + (t + 256) * 16, src + (t + 256) * 16);
        if (t < 128) cpa16(sa0 + (t + 512) * 16, src + (t + 512) * 16);
        asm volatile("cp.async.commit_group;" ::: "memory");
    }

    // ---- fused bias: cs[h] = W[h][256:384] . dec[b] ----
    if (t < Hq) {
        vs[t] = v[t];
        red[0][t] = dec[b * Hq + t];
    }
    __syncthreads();
    {
        const float* dsh = &red[0][0];
#pragma unroll
        for (int r = 0; r < 16; r++) {
            const int h = w * 16 + r;
            float p = 0.f;
#pragma unroll
            for (int i = 0; i < 4; i++)
                p = fmaf(W[h * 384 + 256 + lane + 32 * i], dsh[lane + 32 * i], p);
#pragma unroll
            for (int off = 16; off; off >>= 1)
                p += __shfl_xor_sync(0xffffffffu, p, off);
            if (lane == 0) cs[h] = p;
        }
    }

    float acc[2][8][4];
#pragma unroll
    for (int i = 0; i < 2; i++)
#pragma unroll
        for (int j = 0; j < 8; j++)
#pragma unroll
            for (int q = 0; q < 4; q++) acc[i][j][q] = 0.f;

    const float* base_st = st + (size_t)b * Hq * Nq;
    const float* base_dy = dy + (size_t)b * Hq * Nq;

    // B loader indices (loop-invariant)
    const int bk0 = t >> 5, bc = t & 31;
    const int bk1 = (t + 256) >> 5;

    float4 pb[2][2];

    // ---- prologue: LDG B chunk 0 + pack + STS into buffer 0 ----
    {
        const float* s0 = base_st + (size_t)(2 * bk0) * Nq + n0 + bc * 4;
        const float* s1 = base_st + (size_t)(2 * bk1) * Nq + n0 + bc * 4;
        pb[0][0] = *(const float4*)s0;   pb[0][1] = *(const float4*)(s0 + Nq);
        pb[1][0] = *(const float4*)s1;   pb[1][1] = *(const float4*)(s1 + Nq);

        uint4 b0, b1;
        b0.x = pack2(pb[0][0].x, pb[0][1].x); b0.y = pack2(pb[0][0].y, pb[0][1].y);
        b0.z = pack2(pb[0][0].z, pb[0][1].z); b0.w = pack2(pb[0][0].w, pb[0][1].w);
        b1.x = pack2(pb[1][0].x, pb[1][1].x); b1.y = pack2(pb[1][0].y, pb[1][1].y);
        b1.z = pack2(pb[1][0].z, pb[1][1].z); b1.w = pack2(pb[1][0].w, pb[1][1].w);
        *(uint4*)&Bs16[0][bk0][bc * 4] = b0;
        *(uint4*)&Bs16[0][bk1][bc * 4] = b1;
    }
    asm volatile("cp.async.wait_group 0;" ::: "memory");
    __syncthreads();

    for (int c = 0; c < 8; c++) {
        const int cur = c & 1, nxt = cur ^ 1;

        // ---- issue A cp.async + B LDG for chunk c+1 (drain under MMA) ----
        if (c < 7) {
            const int cn = c + 1;
            const uint32_t sdst = (cn & 1) ? sa1 : sa0;
            const char* src = gA + cn * ACHUNKB;
            cpa16(sdst + t * 16, src + t * 16);
            cpa16(sdst + (t + 256) * 16, src + (t + 256) * 16);
            if (t < 128) cpa16(sdst + (t + 512) * 16, src + (t + 512) * 16);
            asm volatile("cp.async.commit_group;" ::: "memory");

            const int gk0 = cn * BK + 2 * bk0;
            const int gk1 = cn * BK + 2 * bk1;
            const float* s0 = (gk0 < Hq ? base_st + (size_t)gk0 * Nq
                                        : base_dy + (size_t)(gk0 - Hq) * Nq) + n0 + bc * 4;
            const float* s1 = (gk1 < Hq ? base_st + (size_t)gk1 * Nq
                                        : base_dy + (size_t)(gk1 - Hq) * Nq) + n0 + bc * 4;
            pb[0][0] = *(const float4*)s0;   pb[0][1] = *(const float4*)(s0 + Nq);
            pb[1][0] = *(const float4*)s1;   pb[1][1] = *(const float4*)(s1 + Nq);
        }

        // ---- MMA on current buffers ----
#pragma unroll
        for (int kf = 0; kf < 2; kf++) {
            const int k2 = kf * 8;
            uint32_t a[2][4], bb[8][2];
#pragma unroll
            for (int mf = 0; mf < 2; mf++) {
                const int m = wm * 32 + mf * 16;
                a[mf][0] = *(const uint32_t*)&As16[cur][m + gid][k2 + tig];
                a[mf][1] = *(const uint32_t*)&As16[cur][m + gid + 8][k2 + tig];
                a[mf][2] = *(const uint32_t*)&As16[cur][m + gid][k2 + tig + 4];
                a[mf][3] = *(const uint32_t*)&As16[cur][m + gid + 8][k2 + tig + 4];
            }
#pragma unroll
            for (int nf = 0; nf < 8; nf++) {
                const int n = wn * 64 + nf * 8;
                bb[nf][0] = *(const uint32_t*)&Bs16[cur][k2 + tig][n + gid];
                bb[nf][1] = *(const uint32_t*)&Bs16[cur][k2 + tig + 4][n + gid];
            }
#pragma unroll
            for (int mf = 0; mf < 2; mf++)
#pragma unroll
                for (int nf = 0; nf < 8; nf++)
                    mma16(acc[mf][nf], a[mf], bb[nf]);
        }

        // ---- pack + STS B chunk c+1 into other buffer (overlaps MMA) ----
        if (c < 7) {
            uint4 b0, b1;
            b0.x = pack2(pb[0][0].x, pb[0][1].x); b0.y = pack2(pb[0][0].y, pb[0][1].y);
            b0.z = pack2(pb[0][0].z, pb[0][1].z); b0.w = pack2(pb[0][0].w, pb[0][1].w);
            b1.x = pack2(pb[1][0].x, pb[1][1].x); b1.y = pack2(pb[1][0].y, pb[1][1].y);
            b1.z = pack2(pb[1][0].z, pb[1][1].z); b1.w = pack2(pb[1][0].w, pb[1][1].w);
            *(uint4*)&Bs16[nxt][bk0][bc * 4] = b0;
            *(uint4*)&Bs16[nxt][bk1][bc * 4] = b1;
            asm volatile("cp.async.wait_group 0;" ::: "memory");
        }
        __syncthreads();
    }

    // ---- epilogue: tanh + v-dot, reduce over m ----
#pragma unroll
    for (int nf = 0; nf < 8; nf++) {
        float p0 = 0.f, p1 = 0.f;
#pragma unroll
        for (int mf = 0; mf < 2; mf++) {
            const int r0 = wm * 32 + mf * 16 + gid;
            const int r1 = r0 + 8;
            const float v0 = vs[r0], c0 = cs[r0];
            const float v1 = vs[r1], c1 = cs[r1];
            p0 = fmaf(v0, tanh_fast(acc[mf][nf][0] + c0), p0);
            p1 = fmaf(v0, tanh_fast(acc[mf][nf][1] + c0), p1);
            p0 = fmaf(v1, tanh_fast(acc[mf][nf][2] + c1), p0);
            p1 = fmaf(v1, tanh_fast(acc[mf][nf][3] + c1), p1);
        }
#pragma unroll
        for (int off = 4; off < 32; off <<= 1) {
            p0 += __shfl_xor_sync(0xffffffffu, p0, off);
            p1 += __shfl_xor_sync(0xffffffffu, p1, off);
        }
        if (gid == 0) {
            const int col = wn * 64 + nf * 8 + 2 * tig;
            red[wm][col]     = p0;
            red[wm][col + 1] = p1;
        }
    }
    __syncthreads();

    if (t < BN)
        out[(size_t)b * Nq + n0 + t] =
            red[0][t] + red[1][t] + red[2][t] + red[3][t];
}

// ---------------------------------------------------------------------------
// Kernel 2: in-place row softmax over N=2048
// ---------------------------------------------------------------------------
__global__ __launch_bounds__(256) void softmax_kernel(float* __restrict__ out) {
    __shared__ float sm[8];
    const int b = blockIdx.x, t = threadIdx.x;
    const int w = t >> 5, lane = t & 31;
    float* row = out + (size_t)b * Nq;

    float vals[8];
    float m = -1e30f;
#pragma unroll
    for (int i = 0; i < 8; i++) { vals[i] = row[t + 256 * i]; m = fmaxf(m, vals[i]); }
#pragma unroll
    for (int off = 16; off; off >>= 1)
        m = fmaxf(m, __shfl_xor_sync(0xffffffffu, m, off));
    if (lane == 0) sm[w] = m;
    __syncthreads();
    float M = sm[lane & 7];
#pragma unroll
    for (int off = 4; off; off >>= 1)
        M = fmaxf(M, __shfl_xor_sync(0xffffffffu, M, off));

    float sum = 0.f;
#pragma unroll
    for (int i = 0; i < 8; i++) { vals[i] = __expf(vals[i] - M); sum += vals[i]; }
#pragma unroll
    for (int off = 16; off; off >>= 1)
        sum += __shfl_xor_sync(0xffffffffu, sum, off);
    __syncthreads();
    if (lane == 0) sm[w] = sum;
    __syncthreads();
    float S = sm[lane & 7];
#pragma unroll
    for (int off = 4; off; off >>= 1)
        S += __shfl_xor_sync(0xffffffffu, S, off);

    const float inv = 1.f / S;
#pragma unroll
    for (int i = 0; i < 8; i++) row[t + 256 * i] = vals[i] * inv;
}

// ---------------------------------------------------------------------------
extern "C" void kernel_launch(void* const* d_in, const int* in_sizes, int n_in,
                              void* d_out, int out_size) {
    const float* st  = (const float*)d_in[0];
    const float* dy  = (const float*)d_in[1];
    const float* dec = (const float*)d_in[2];
    const float* v   = (const float*)d_in[3];
    const float* W   = (const float*)d_in[4];
    float* out = (float*)d_out;

    pack_kernel<<<128, 256>>>(W);
    score_kernel<<<dim3(Nq / BN, Bq), 256>>>(st, dy, dec, v, W, out);
    softmax_kernel<<<Bq, 256>>>(out);
}